// round 1
// baseline (speedup 1.0000x reference)
#include <cuda_runtime.h>
#include <cuda_bf16.h>
#include <math_constants.h>

// Problem constants
#define Bc 4
#define Nn 4096          // H*W
#define Cc 1024
#define BNN (4ull * 4096ull * 4096ull)

// ---------------- device scratch (no allocations allowed) ----------------
__device__ float g_fn[(size_t)Bc * Nn * Cc];   // normalized embeddings, 64MB
__device__ float g_rowval[Bc * Nn];            // max over non-ref cols (inf for non-ref rows)
__device__ int   g_mask[Bc * Nn];              // expanded 0/1 mask
__device__ int   g_k[Bc];                      // #ref per batch
__device__ float g_thresh[Bc];
__device__ int   g_mask_mode;                  // 0=u8, 1=i32, 2=f32

// ---------------- 1) classify mask dtype ----------------
// Reads only the first 4096 32-bit words: that covers all data if u8 (16384B),
// and the first 4096 elements (all of batch 0, which contains a guaranteed True)
// if i32/f32. Decides decode mode.
__global__ void classify_kernel(const unsigned* __restrict__ masks) {
    __shared__ int okI, okF;
    if (threadIdx.x == 0) {
        okI = 1; okF = 1;
        g_k[0] = 0; g_k[1] = 0; g_k[2] = 0; g_k[3] = 0;
    }
    __syncthreads();
    for (int i = threadIdx.x; i < 4096; i += blockDim.x) {
        unsigned w = masks[i];
        if (w != 0u && w != 1u)          okI = 0;
        if (w != 0u && w != 0x3F800000u) okF = 0;
    }
    __syncthreads();
    if (threadIdx.x == 0) {
        g_mask_mode = okF ? 2 : (okI ? 1 : 0);
    }
}

// ---------------- 2) expand mask + count refs ----------------
__global__ void expand_kernel(const void* __restrict__ masks) {
    int idx = blockIdx.x * blockDim.x + threadIdx.x;
    if (idx >= Bc * Nn) return;
    int mode = g_mask_mode;
    int v;
    if (mode == 0)      v = (((const unsigned char*)masks)[idx] != 0);
    else if (mode == 1) v = (((const int*)masks)[idx] != 0);
    else                v = (((const float*)masks)[idx] != 0.0f);
    g_mask[idx] = v;
    if (v) atomicAdd(&g_k[idx >> 12], 1);
}

// ---------------- 3) normalize rows ----------------
// one block per (b,n) row; 256 threads x float4 = 1024 elems
__global__ void normalize_kernel(const float* __restrict__ x) {
    size_t row = blockIdx.x;
    const float4* xr = (const float4*)(x + row * (size_t)Cc);
    float4* fr = (float4*)(g_fn + row * (size_t)Cc);
    float4 v = xr[threadIdx.x];
    float ss = v.x * v.x + v.y * v.y + v.z * v.z + v.w * v.w;
    #pragma unroll
    for (int o = 16; o > 0; o >>= 1) ss += __shfl_xor_sync(0xFFFFFFFFu, ss, o);
    __shared__ float red[8];
    int lane = threadIdx.x & 31, wid = threadIdx.x >> 5;
    if (lane == 0) red[wid] = ss;
    __syncthreads();
    __shared__ float stotal;
    if (threadIdx.x == 0) {
        float t = 0.f;
        #pragma unroll
        for (int i = 0; i < 8; i++) t += red[i];
        stotal = t;
    }
    __syncthreads();
    float inv = 1.0f / fmaxf(sqrtf(stotal), 1e-12f);
    float4 o = make_float4(v.x * inv, v.y * inv, v.z * inv, v.w * inv);
    fr[threadIdx.x] = o;
}

// ---------------- 4) fp32 GEMM: sim[b] = fn[b] @ fn[b]^T ----------------
// 128x128 block tile, BK=8, 256 threads, 8x8 per thread in 4 quadrants.
__global__ void __launch_bounds__(256) gemm_kernel(float* __restrict__ simOut) {
    const int b = blockIdx.z;
    const float* A = g_fn + (size_t)b * Nn * Cc;
    float* Cout = simOut + (size_t)b * Nn * Nn;
    const int rowBase = blockIdx.y * 128;
    const int colBase = blockIdx.x * 128;

    __shared__ float As[8][128];
    __shared__ float Bs[8][128];

    const int tid = threadIdx.x;
    const int tx = tid & 15;       // 0..15
    const int ty = tid >> 4;       // 0..15

    float acc[8][8];
    #pragma unroll
    for (int i = 0; i < 8; i++)
        #pragma unroll
        for (int j = 0; j < 8; j++) acc[i][j] = 0.0f;

    const int lrow = tid >> 1;           // 0..127
    const int lk4  = (tid & 1) * 4;      // 0 or 4
    const float* Aload = A + (size_t)(rowBase + lrow) * Cc + lk4;
    const float* Bload = A + (size_t)(colBase + lrow) * Cc + lk4;

    for (int k0 = 0; k0 < Cc; k0 += 8) {
        float4 a4 = *(const float4*)(Aload + k0);
        float4 b4 = *(const float4*)(Bload + k0);
        As[lk4 + 0][lrow] = a4.x; As[lk4 + 1][lrow] = a4.y;
        As[lk4 + 2][lrow] = a4.z; As[lk4 + 3][lrow] = a4.w;
        Bs[lk4 + 0][lrow] = b4.x; Bs[lk4 + 1][lrow] = b4.y;
        Bs[lk4 + 2][lrow] = b4.z; Bs[lk4 + 3][lrow] = b4.w;
        __syncthreads();

        #pragma unroll
        for (int k = 0; k < 8; k++) {
            float4 m0 = *(const float4*)&As[k][ty * 4];
            float4 m1 = *(const float4*)&As[k][64 + ty * 4];
            float4 n0 = *(const float4*)&Bs[k][tx * 4];
            float4 n1 = *(const float4*)&Bs[k][64 + tx * 4];
            float rm[8] = {m0.x, m0.y, m0.z, m0.w, m1.x, m1.y, m1.z, m1.w};
            float rn[8] = {n0.x, n0.y, n0.z, n0.w, n1.x, n1.y, n1.z, n1.w};
            #pragma unroll
            for (int i = 0; i < 8; i++)
                #pragma unroll
                for (int j = 0; j < 8; j++)
                    acc[i][j] = fmaf(rm[i], rn[j], acc[i][j]);
        }
        __syncthreads();
    }

    #pragma unroll
    for (int i = 0; i < 8; i++) {
        int r = rowBase + ((i < 4) ? (ty * 4 + i) : (64 + ty * 4 + (i - 4)));
        float* cp = Cout + (size_t)r * Nn + colBase;
        *(float4*)(cp + tx * 4)      = make_float4(acc[i][0], acc[i][1], acc[i][2], acc[i][3]);
        *(float4*)(cp + 64 + tx * 4) = make_float4(acc[i][4], acc[i][5], acc[i][6], acc[i][7]);
    }
}

// ---------------- 5) per ref-row max over non-ref cols ----------------
__global__ void rowmax_kernel(const float* __restrict__ simIn) {
    const int bi = blockIdx.x;          // b*4096 + i
    const int b = bi >> 12;
    if (!g_mask[bi]) {
        if (threadIdx.x == 0) g_rowval[bi] = CUDART_INF_F;
        return;
    }
    const float* row = simIn + (size_t)bi * Nn;
    const int* mj = &g_mask[b << 12];
    float mx = -CUDART_INF_F;
    for (int j = threadIdx.x; j < Nn; j += 256) {
        if (!mj[j]) mx = fmaxf(mx, row[j]);
    }
    #pragma unroll
    for (int o = 16; o > 0; o >>= 1) mx = fmaxf(mx, __shfl_xor_sync(0xFFFFFFFFu, mx, o));
    __shared__ float red[8];
    int lane = threadIdx.x & 31, wid = threadIdx.x >> 5;
    if (lane == 0) red[wid] = mx;
    __syncthreads();
    if (threadIdx.x == 0) {
        float t = -CUDART_INF_F;
        #pragma unroll
        for (int i = 0; i < 8; i++) t = fmaxf(t, red[i]);
        g_rowval[bi] = t;
    }
}

// ---------------- 6) per-batch lower median of ref maxes ----------------
// bitonic sort of 4096 values (non-ref rows are +inf so they sort last)
__global__ void median_kernel(float* __restrict__ outThresh) {
    __shared__ float s[4096];
    const int b = blockIdx.x;
    for (int i = threadIdx.x; i < 4096; i += blockDim.x) s[i] = g_rowval[(b << 12) + i];
    __syncthreads();
    for (int kk = 2; kk <= 4096; kk <<= 1) {
        for (int j = kk >> 1; j > 0; j >>= 1) {
            for (int i = threadIdx.x; i < 4096; i += blockDim.x) {
                int ixj = i ^ j;
                if (ixj > i) {
                    bool up = ((i & kk) == 0);
                    float a = s[i], c = s[ixj];
                    if ((a > c) == up) { s[i] = c; s[ixj] = a; }
                }
            }
            __syncthreads();
        }
    }
    if (threadIdx.x == 0) {
        int cnt = g_k[b];
        float t = s[(cnt - 1) >> 1];
        g_thresh[b] = t;
        outThresh[b] = t;
    }
}

// ---------------- 7) match write ----------------
__global__ void match_kernel(const float* __restrict__ simIn, float* __restrict__ matchOut) {
    size_t g = (size_t)blockIdx.x * blockDim.x + threadIdx.x;
    size_t base = g * 4;                    // element index into [B,N,N]
    if (base >= BNN) return;
    int j = (int)(base & 4095);
    size_t bi = base >> 12;
    int i = (int)(bi & 4095);
    int b = (int)(bi >> 12);

    int mi = g_mask[(b << 12) + i];
    float4 o;
    if (!mi) {
        o = make_float4(0.f, 0.f, 0.f, 0.f);
    } else {
        float th = g_thresh[b];
        float4 s4 = *(const float4*)(simIn + base);
        const int* mj = &g_mask[(b << 12) + j];
        o.x = (!mj[0] && s4.x > th) ? 1.0f : 0.0f;
        o.y = (!mj[1] && s4.y > th) ? 1.0f : 0.0f;
        o.z = (!mj[2] && s4.z > th) ? 1.0f : 0.0f;
        o.w = (!mj[3] && s4.w > th) ? 1.0f : 0.0f;
    }
    *(float4*)(matchOut + base) = o;
}

// ---------------- launch ----------------
extern "C" void kernel_launch(void* const* d_in, const int* in_sizes, int n_in,
                              void* d_out, int out_size) {
    const float* emb = (const float*)d_in[0];
    const void* masks = d_in[1];
    float* out = (float*)d_out;

    float* matchOut  = out;               // [B,N,N] as 0/1 floats
    float* simOut    = out + BNN;         // [B,N,N]
    float* threshOut = out + 2 * BNN;     // [B]

    classify_kernel<<<1, 256>>>((const unsigned*)masks);
    expand_kernel<<<(Bc * Nn + 255) / 256, 256>>>(masks);
    normalize_kernel<<<Bc * Nn, 256>>>(emb);
    gemm_kernel<<<dim3(Nn / 128, Nn / 128, Bc), 256>>>(simOut);
    rowmax_kernel<<<Bc * Nn, 256>>>(simOut);
    median_kernel<<<Bc, 1024>>>(threshOut);
    match_kernel<<<(unsigned)((BNN / 4 + 255) / 256), 256>>>(simOut, matchOut);
}

// round 3
// speedup vs baseline: 4.9754x; 4.9754x over previous
#include <cuda_runtime.h>
#include <cuda_bf16.h>
#include <math_constants.h>
#include <cstdint>

// Problem constants
#define Bc 4
#define Nn 4096          // H*W
#define Cc 1024
#define BNN (4ull * 4096ull * 4096ull)

// ---------------- device scratch (no allocations allowed) ----------------
__device__ __nv_bfloat16 g_hi[(size_t)Bc * Nn * Cc];   // bf16 hi part of normalized emb
__device__ __nv_bfloat16 g_lo[(size_t)Bc * Nn * Cc];   // bf16 lo part
__device__ unsigned g_rowmax[Bc * Nn];                 // order-encoded max over non-ref cols
__device__ int   g_mask[Bc * Nn];                      // expanded 0/1 mask
__device__ int   g_k[Bc];                              // #ref per batch
__device__ float g_thresh[Bc];
__device__ int   g_mask_mode;                          // 0=u8, 1=i32, 2=f32

// order-preserving float <-> uint encode (for atomicMax on signed floats)
__device__ __forceinline__ unsigned ordenc(float f) {
    unsigned u = __float_as_uint(f);
    return (u & 0x80000000u) ? ~u : (u | 0x80000000u);
}
__device__ __forceinline__ float orddec(unsigned u) {
    return (u & 0x80000000u) ? __uint_as_float(u ^ 0x80000000u) : __uint_as_float(~u);
}
#define ORDENC_NEGINF 0x007FFFFFu   // ordenc(-inf)

__device__ __forceinline__ uint32_t smem_to_u32(const void* smem_ptr) {
    uint32_t addr;
    asm("{ .reg .u64 tmp; cvta.to.shared.u64 tmp, %1; cvt.u32.u64 %0, tmp; }"
        : "=r"(addr) : "l"(smem_ptr));
    return addr;
}

// ---------------- 1) classify mask dtype ----------------
__global__ void classify_kernel(const unsigned* __restrict__ masks) {
    __shared__ int okI, okF;
    if (threadIdx.x == 0) {
        okI = 1; okF = 1;
        g_k[0] = 0; g_k[1] = 0; g_k[2] = 0; g_k[3] = 0;
    }
    __syncthreads();
    for (int i = threadIdx.x; i < 4096; i += blockDim.x) {
        unsigned w = masks[i];
        if (w != 0u && w != 1u)          okI = 0;
        if (w != 0u && w != 0x3F800000u) okF = 0;
    }
    __syncthreads();
    if (threadIdx.x == 0) g_mask_mode = okF ? 2 : (okI ? 1 : 0);
}

// ---------------- 2) expand mask + count refs + init rowmax ----------------
__global__ void expand_kernel(const void* __restrict__ masks) {
    int idx = blockIdx.x * blockDim.x + threadIdx.x;
    if (idx >= Bc * Nn) return;
    int mode = g_mask_mode;
    int v;
    if (mode == 0)      v = (((const unsigned char*)masks)[idx] != 0);
    else if (mode == 1) v = (((const int*)masks)[idx] != 0);
    else                v = (((const float*)masks)[idx] != 0.0f);
    g_mask[idx] = v;
    g_rowmax[idx] = ORDENC_NEGINF;
    if (v) atomicAdd(&g_k[idx >> 12], 1);
}

// ---------------- 3) normalize rows -> bf16 hi/lo split ----------------
__global__ void normalize_kernel(const float* __restrict__ x) {
    size_t row = blockIdx.x;
    const float4* xr = (const float4*)(x + row * (size_t)Cc);
    float4 v = xr[threadIdx.x];
    float ss = v.x * v.x + v.y * v.y + v.z * v.z + v.w * v.w;
    #pragma unroll
    for (int o = 16; o > 0; o >>= 1) ss += __shfl_xor_sync(0xFFFFFFFFu, ss, o);
    __shared__ float red[8];
    int lane = threadIdx.x & 31, wid = threadIdx.x >> 5;
    if (lane == 0) red[wid] = ss;
    __syncthreads();
    __shared__ float stotal;
    if (threadIdx.x == 0) {
        float t = 0.f;
        #pragma unroll
        for (int i = 0; i < 8; i++) t += red[i];
        stotal = t;
    }
    __syncthreads();
    float inv = 1.0f / fmaxf(sqrtf(stotal), 1e-12f);
    float y[4] = {v.x * inv, v.y * inv, v.z * inv, v.w * inv};
    __nv_bfloat16 h[4]; float lo[4];
    #pragma unroll
    for (int i = 0; i < 4; i++) {
        h[i] = __float2bfloat16(y[i]);
        lo[i] = y[i] - __bfloat162float(h[i]);
    }
    __nv_bfloat162* hp = (__nv_bfloat162*)(g_hi + row * (size_t)Cc);
    __nv_bfloat162* lp = (__nv_bfloat162*)(g_lo + row * (size_t)Cc);
    hp[threadIdx.x * 2]     = __nv_bfloat162(h[0], h[1]);
    hp[threadIdx.x * 2 + 1] = __nv_bfloat162(h[2], h[3]);
    lp[threadIdx.x * 2]     = __nv_bfloat162(__float2bfloat16(lo[0]), __float2bfloat16(lo[1]));
    lp[threadIdx.x * 2 + 1] = __nv_bfloat162(__float2bfloat16(lo[2]), __float2bfloat16(lo[3]));
}

// ---------------- 4) mma.sync bf16x3 GEMM over lower-triangular tiles ----------------
// CTA tile 128x128, BK=64 bf16 (=128B rows), 8 warps (4 M x 2 N), warp tile 32x64.
// Virtual K = 3*1024: region 0: hi.hi, region 1: lo.hi, region 2: hi.lo.
#define BM 128
#define BK 64
#define NKCHUNK 48           // 3*1024/64

// smem: tile region (also used as f32 tile in epilogue, stride 129):
//   pipeline: A buf s at s*16384 ; B buf s at 32768 + s*16384  (64KB)
//   epilogue: f32 tile 128*129*4 = 66048
// col masks (persist): cmT at 66048 (tj cols), cmI at 66560 (ti cols)
#define SM_CMT 66048
#define SM_CMI 66560
#define SM_TOTAL 67072

__device__ __forceinline__ void ldmx4(uint32_t* r, uint32_t addr) {
    asm volatile("ldmatrix.sync.aligned.m8n8.x4.shared.b16 {%0,%1,%2,%3}, [%4];"
                 : "=r"(r[0]), "=r"(r[1]), "=r"(r[2]), "=r"(r[3]) : "r"(addr));
}
__device__ __forceinline__ void mma16816(float* d, const uint32_t* a, const uint32_t* b) {
    asm volatile(
        "mma.sync.aligned.m16n8k16.row.col.f32.bf16.bf16.f32 "
        "{%0,%1,%2,%3}, {%4,%5,%6,%7}, {%8,%9}, {%0,%1,%2,%3};"
        : "+f"(d[0]), "+f"(d[1]), "+f"(d[2]), "+f"(d[3])
        : "r"(a[0]), "r"(a[1]), "r"(a[2]), "r"(a[3]), "r"(b[0]), "r"(b[1]));
}

__device__ __forceinline__ void stage_load(uint32_t smA, uint32_t smB,
        const __nv_bfloat16* __restrict__ gA, const __nv_bfloat16* __restrict__ gB,
        int rowBase, int colBase, int koff, int tid) {
    #pragma unroll
    for (int it = 0; it < 4; it++) {
        int i = tid + it * 256;
        int row = i >> 3, c = i & 7;
        uint32_t off = row * 128 + (((unsigned)(c ^ (row & 7))) << 4);
        const void* ga = gA + (((size_t)(rowBase + row)) << 10) + koff + c * 8;
        const void* gb = gB + (((size_t)(colBase + row)) << 10) + koff + c * 8;
        asm volatile("cp.async.cg.shared.global [%0], [%1], 16;" :: "r"(smA + off), "l"(ga));
        asm volatile("cp.async.cg.shared.global [%0], [%1], 16;" :: "r"(smB + off), "l"(gb));
    }
}

__global__ void __launch_bounds__(256, 2) gemm_kernel(float* __restrict__ simOut) {
    extern __shared__ char smem[];
    const uint32_t sb = smem_to_u32(smem);
    const int tid = threadIdx.x;
    const int lane = tid & 31, wid = tid >> 5;
    const int b = blockIdx.z;

    // triangular tile decode: t -> (ti >= tj)
    int t = blockIdx.x;
    int ti = (int)((sqrtf(8.0f * (float)t + 1.0f) - 1.0f) * 0.5f);
    while ((ti + 1) * (ti + 2) / 2 <= t) ti++;
    while (ti * (ti + 1) / 2 > t) ti--;
    int tj = t - ti * (ti + 1) / 2;
    const int rowBase = ti * BM;
    const int colBase = tj * BM;

    // col masks (addend: -inf on ref cols)
    if (tid < 128)
        ((float*)(smem + SM_CMT))[tid] = g_mask[(b << 12) + colBase + tid] ? -CUDART_INF_F : 0.0f;
    else
        ((float*)(smem + SM_CMI))[tid - 128] = g_mask[(b << 12) + rowBase + (tid - 128)] ? -CUDART_INF_F : 0.0f;

    const __nv_bfloat16* gH = g_hi + (size_t)b * Nn * Cc;
    const __nv_bfloat16* gL = g_lo + (size_t)b * Nn * Cc;

    float acc[2][8][4];
    #pragma unroll
    for (int mt = 0; mt < 2; mt++)
        #pragma unroll
        for (int nt = 0; nt < 8; nt++)
            #pragma unroll
            for (int q = 0; q < 4; q++) acc[mt][nt][q] = 0.0f;

    const int wm = wid >> 1;         // 0..3 -> M
    const int wn = wid & 1;          // 0..1 -> N
    const int wmBase = wm * 32;
    const int wnBase = wn * 64;

    // prefetch chunk 0 (region 0: hi,hi)
    stage_load(sb, sb + 32768, gH, gH, rowBase, colBase, 0, tid);
    asm volatile("cp.async.commit_group;");

    for (int kc = 0; kc < NKCHUNK; kc++) {
        asm volatile("cp.async.wait_group 0;");
        __syncthreads();
        if (kc + 1 < NKCHUNK) {
            int nk = kc + 1;
            int r = nk >> 4;
            int ko = (nk & 15) << 6;
            const __nv_bfloat16* sA = (r == 1) ? gL : gH;
            const __nv_bfloat16* sB = (r == 2) ? gL : gH;
            int s = nk & 1;
            stage_load(sb + s * 16384, sb + 32768 + s * 16384, sA, sB, rowBase, colBase, ko, tid);
            asm volatile("cp.async.commit_group;");
        }
        const uint32_t smA = sb + (kc & 1) * 16384;
        const uint32_t smB = sb + 32768 + (kc & 1) * 16384;

        #pragma unroll
        for (int ks = 0; ks < 4; ks++) {
            uint32_t afr[2][4];
            #pragma unroll
            for (int mt = 0; mt < 2; mt++) {
                int row = wmBase + mt * 16 + (lane & 7) + ((lane >> 3) & 1) * 8;
                int chunk = ks * 2 + (lane >> 4);
                ldmx4(afr[mt], smA + row * 128 + (((unsigned)(chunk ^ (row & 7))) << 4));
            }
            uint32_t bfr[8][2];
            #pragma unroll
            for (int bt = 0; bt < 4; bt++) {
                int nrow = wnBase + bt * 16 + (lane & 7) + (lane >> 4) * 8;
                int chunk = ks * 2 + ((lane >> 3) & 1);
                uint32_t r4[4];
                ldmx4(r4, smB + nrow * 128 + (((unsigned)(chunk ^ (nrow & 7))) << 4));
                bfr[bt * 2][0] = r4[0]; bfr[bt * 2][1] = r4[1];
                bfr[bt * 2 + 1][0] = r4[2]; bfr[bt * 2 + 1][1] = r4[3];
            }
            #pragma unroll
            for (int mt = 0; mt < 2; mt++)
                #pragma unroll
                for (int nt = 0; nt < 8; nt++)
                    mma16816(acc[mt][nt], afr[mt], bfr[nt]);
        }
        __syncthreads();
    }

    // ---------- epilogue: stage f32 tile in smem (stride 129) ----------
    float* tile = (float*)smem;
    #pragma unroll
    for (int mt = 0; mt < 2; mt++) {
        #pragma unroll
        for (int nt = 0; nt < 8; nt++) {
            int r = wmBase + mt * 16 + (lane >> 2);
            int c = wnBase + nt * 8 + 2 * (lane & 3);
            tile[r * 129 + c]       = acc[mt][nt][0];
            tile[r * 129 + c + 1]   = acc[mt][nt][1];
            tile[(r + 8) * 129 + c]     = acc[mt][nt][2];
            tile[(r + 8) * 129 + c + 1] = acc[mt][nt][3];
        }
    }
    __syncthreads();

    const float* cmT = (const float*)(smem + SM_CMT);
    const float* cmI = (const float*)(smem + SM_CMI);
    float* simB = simOut + (size_t)b * Nn * Nn;

    // direct tile: rows rowBase.., cols colBase..
    {
        float cm0 = cmT[4 * lane], cm1 = cmT[4 * lane + 1], cm2 = cmT[4 * lane + 2], cm3 = cmT[4 * lane + 3];
        #pragma unroll 4
        for (int rr = 0; rr < 16; rr++) {
            int r = wid * 16 + rr;
            const float* tr = tile + r * 129 + 4 * lane;
            float v0 = tr[0], v1 = tr[1], v2 = tr[2], v3 = tr[3];
            *(float4*)(simB + (size_t)(rowBase + r) * Nn + colBase + 4 * lane) =
                make_float4(v0, v1, v2, v3);
            float mx = fmaxf(fmaxf(v0 + cm0, v1 + cm1), fmaxf(v2 + cm2, v3 + cm3));
            #pragma unroll
            for (int o = 16; o > 0; o >>= 1) mx = fmaxf(mx, __shfl_xor_sync(0xFFFFFFFFu, mx, o));
            if (lane == 0 && g_mask[(b << 12) + rowBase + r])
                atomicMax(&g_rowmax[(b << 12) + rowBase + r], ordenc(mx));
        }
    }
    // mirror tile (skip diagonal): rows colBase.., cols rowBase..
    if (ti != tj) {
        float cm0 = cmI[4 * lane], cm1 = cmI[4 * lane + 1], cm2 = cmI[4 * lane + 2], cm3 = cmI[4 * lane + 3];
        #pragma unroll 4
        for (int rr = 0; rr < 16; rr++) {
            int j = wid * 16 + rr;
            float v0 = tile[(4 * lane + 0) * 129 + j];
            float v1 = tile[(4 * lane + 1) * 129 + j];
            float v2 = tile[(4 * lane + 2) * 129 + j];
            float v3 = tile[(4 * lane + 3) * 129 + j];
            *(float4*)(simB + (size_t)(colBase + j) * Nn + rowBase + 4 * lane) =
                make_float4(v0, v1, v2, v3);
            float mx = fmaxf(fmaxf(v0 + cm0, v1 + cm1), fmaxf(v2 + cm2, v3 + cm3));
            #pragma unroll
            for (int o = 16; o > 0; o >>= 1) mx = fmaxf(mx, __shfl_xor_sync(0xFFFFFFFFu, mx, o));
            if (lane == 0 && g_mask[(b << 12) + colBase + j])
                atomicMax(&g_rowmax[(b << 12) + colBase + j], ordenc(mx));
        }
    }
}

// ---------------- 5) per-batch lower median of ref maxes ----------------
__global__ void median_kernel(float* __restrict__ outThresh) {
    __shared__ float s[4096];
    const int b = blockIdx.x;
    for (int i = threadIdx.x; i < 4096; i += blockDim.x) {
        int idx = (b << 12) + i;
        s[i] = g_mask[idx] ? orddec(g_rowmax[idx]) : CUDART_INF_F;
    }
    __syncthreads();
    for (int kk = 2; kk <= 4096; kk <<= 1) {
        for (int j = kk >> 1; j > 0; j >>= 1) {
            for (int i = threadIdx.x; i < 4096; i += blockDim.x) {
                int ixj = i ^ j;
                if (ixj > i) {
                    bool up = ((i & kk) == 0);
                    float a = s[i], c = s[ixj];
                    if ((a > c) == up) { s[i] = c; s[ixj] = a; }
                }
            }
            __syncthreads();
        }
    }
    if (threadIdx.x == 0) {
        int cnt = g_k[b];
        float t = s[(cnt - 1) >> 1];
        g_thresh[b] = t;
        outThresh[b] = t;
    }
}

// ---------------- 6) match write ----------------
__global__ void match_kernel(const float* __restrict__ simIn, float* __restrict__ matchOut) {
    size_t g = (size_t)blockIdx.x * blockDim.x + threadIdx.x;
    size_t base = g * 4;
    if (base >= BNN) return;
    int j = (int)(base & 4095);
    size_t bi = base >> 12;
    int i = (int)(bi & 4095);
    int b = (int)(bi >> 12);

    int mi = g_mask[(b << 12) + i];
    float4 o;
    if (!mi) {
        o = make_float4(0.f, 0.f, 0.f, 0.f);
    } else {
        float th = g_thresh[b];
        float4 s4 = *(const float4*)(simIn + base);
        const int* mj = &g_mask[(b << 12) + j];
        o.x = (!mj[0] && s4.x > th) ? 1.0f : 0.0f;
        o.y = (!mj[1] && s4.y > th) ? 1.0f : 0.0f;
        o.z = (!mj[2] && s4.z > th) ? 1.0f : 0.0f;
        o.w = (!mj[3] && s4.w > th) ? 1.0f : 0.0f;
    }
    *(float4*)(matchOut + base) = o;
}

// ---------------- launch ----------------
extern "C" void kernel_launch(void* const* d_in, const int* in_sizes, int n_in,
                              void* d_out, int out_size) {
    const float* emb = (const float*)d_in[0];
    const void* masks = d_in[1];
    float* out = (float*)d_out;

    float* matchOut  = out;               // [B,N,N] as 0/1 floats
    float* simOut    = out + BNN;         // [B,N,N]
    float* threshOut = out + 2 * BNN;     // [B]

    cudaFuncSetAttribute(gemm_kernel, cudaFuncAttributeMaxDynamicSharedMemorySize, SM_TOTAL);

    classify_kernel<<<1, 256>>>((const unsigned*)masks);
    expand_kernel<<<(Bc * Nn + 255) / 256, 256>>>(masks);
    normalize_kernel<<<Bc * Nn, 256>>>(emb);
    const int NTILE = Nn / BM;                         // 32
    const int NPAIR = NTILE * (NTILE + 1) / 2;         // 528
    gemm_kernel<<<dim3(NPAIR, 1, Bc), 256, SM_TOTAL>>>(simOut);
    median_kernel<<<Bc, 1024>>>(threshOut);
    match_kernel<<<(unsigned)((BNN / 4 + 255) / 256), 256>>>(simOut, matchOut);
}